// round 15
// baseline (speedup 1.0000x reference)
#include <cuda_runtime.h>
#include <math.h>
#include <stdint.h>

// Problem constants
#define GROUPS 4
#define NNODE  4096
#define KDIM   128
#define TILE   128
#define NB     (NNODE / TILE)
#define NPAIRS (NB * (NB + 1) / 2)   // 528
#define NTHREADS 512

#define T_LOGIT    0.40546510810816f   // ln(1.5) = logit(0.6)
#define FIX_EPS    1e-3f               // >> tf32-split error (~1e-5): flip-proof band
#define XPREFILTER 0.4f

// smem: fragment-staged tf32 tiles for one K-half (64) of A(128 rows) and B(128 cols)
// A: 8 ksteps x 8 mtiles x 128 floats = 32KB per split
// B: 8 ksteps x 16 ntiles x 64 floats = 32KB per split
#define SM_AHI 0
#define SM_ALO 32768
#define SM_BHI 65536
#define SM_BLO 98304
#define SMEM_TOTAL 131072

// ---- tf32 helpers ----
__device__ __forceinline__ uint32_t tf32_rna(float f) {
    uint32_t r; asm("cvt.rna.tf32.f32 %0, %1;" : "=r"(r) : "f"(f)); return r;
}

// mma.sync m16n8k8 tf32: A row-major (4 regs), B col-major (2 regs), C fp32 (4 regs)
__device__ __forceinline__ void mma8(float* d, const uint32_t* a, const uint32_t* b) {
    asm("mma.sync.aligned.m16n8k8.row.col.f32.tf32.tf32.f32 "
        "{%0,%1,%2,%3}, {%4,%5,%6,%7}, {%8,%9}, {%0,%1,%2,%3};"
        : "+f"(d[0]), "+f"(d[1]), "+f"(d[2]), "+f"(d[3])
        : "r"(a[0]), "r"(a[1]), "r"(a[2]), "r"(a[3]), "r"(b[0]), "r"(b[1]));
}

// exact fp32 dot, k-ascending fmaf — identical arithmetic to the validated
// SIMT kernel (rel_err 3e-8, zero threshold flips across 5 benches)
__device__ __noinline__ float exact_dot(const float* __restrict__ a, const float* __restrict__ b) {
    float acc = 0.0f;
    #pragma unroll 4
    for (int k = 0; k < KDIM; k++) acc = fmaf(a[k], b[k], acc);
    return acc;
}

__device__ __forceinline__ float finish(float x, const float* __restrict__ Arow,
                                        const float* __restrict__ Brow) {
    if (fabsf(x - T_LOGIT) < FIX_EPS) x = exact_dot(Arow, Brow);   // flip-proof
    float r = 0.0f;
    if (x > XPREFILTER) {
        const float s = 1.0f / (1.0f + expf(-x));
        r = (s < 0.6f) ? 0.0f : s;
    }
    return r;
}

__global__ __launch_bounds__(NTHREADS, 1)
void bridge_tf32_kernel(const float* __restrict__ nodes, float* __restrict__ out)
{
    // ---- upper-triangle block pair (bi <= bj) ----
    const int t = blockIdx.x;
    int bi = (int)((float)NB + 0.5f - sqrtf(((float)NB + 0.5f) * ((float)NB + 0.5f) - 2.0f * (float)t));
    if (bi < 0) bi = 0;
    if (bi >= NB) bi = NB - 1;
    while (bi + 1 <= NB - 1 && ((bi + 1) * NB - (bi + 1) * bi / 2) <= t) bi++;
    while (bi > 0 && (bi * NB - bi * (bi - 1) / 2) > t) bi--;
    const int bj = bi + (t - (bi * NB - bi * (bi - 1) / 2));

    const int g    = blockIdx.y;
    const int row0 = bi * TILE;
    const int col0 = bj * TILE;
    const bool mirror = (bi != bj);

    const float* __restrict__ A = nodes + (size_t)g * NNODE * KDIM;
    float* __restrict__ C       = out   + (size_t)g * NNODE * (size_t)NNODE;

    extern __shared__ char smem[];
    uint32_t* AHI = (uint32_t*)(smem + SM_AHI);
    uint32_t* ALO = (uint32_t*)(smem + SM_ALO);
    uint32_t* BHI = (uint32_t*)(smem + SM_BHI);
    uint32_t* BLO = (uint32_t*)(smem + SM_BLO);

    const int tid  = threadIdx.x;
    const int wid  = tid >> 5;
    const int lane = tid & 31;
    const int grp  = lane >> 2;       // groupID 0..7
    const int tig  = lane & 3;        // thread-in-group
    const int wr   = wid >> 2;        // warp row 0..3 (32 rows each)
    const int wc   = wid & 3;         // warp col 0..3 (32 cols each)

    float acc[2][4][4];
    #pragma unroll
    for (int i = 0; i < 2; i++)
        #pragma unroll
        for (int j = 0; j < 4; j++)
            #pragma unroll
            for (int q = 0; q < 4; q++)
                acc[i][j][q] = 0.0f;

    // ---- two K-phases of 64 ----
    for (int p = 0; p < 2; p++) {
        if (p) __syncthreads();   // protect previous phase's fragments until consumed

        // load + split + scatter into fragment-major smem
        // 2048 float4 per matrix per phase; thread handles 4 (A) + 4 (B)
        #pragma unroll
        for (int l = 0; l < 4; l++) {
            const int f  = tid + l * NTHREADS;     // 0..2047
            const int m  = f >> 4;                 // 0..127
            const int q4 = f & 15;                 // float4 within 64-k half

            // A block (rows)
            {
                const float4 v = *(const float4*)(A + (size_t)(row0 + m) * KDIM + p * 64 + q4 * 4);
                const float fv[4] = {v.x, v.y, v.z, v.w};
                #pragma unroll
                for (int e = 0; e < 4; e++) {
                    const int k  = q4 * 4 + e;           // 0..63
                    const uint32_t hb = tf32_rna(fv[e]);
                    const float lo = fv[e] - __uint_as_float(hb);   // exact
                    const uint32_t lb = tf32_rna(lo);
                    const int r = m & 15, c = k & 7;
                    const int fl   = (((r & 7) << 2) | (c & 3));
                    const int reg  = (r >> 3) | ((c >> 2) << 1);
                    const int fi   = (((k >> 3) << 3) + (m >> 4)) * 128 + (fl << 2) + reg;
                    AHI[fi] = hb; ALO[fi] = lb;
                }
            }
            // B block (cols)
            {
                const float4 v = *(const float4*)(A + (size_t)(col0 + m) * KDIM + p * 64 + q4 * 4);
                const float fv[4] = {v.x, v.y, v.z, v.w};
                #pragma unroll
                for (int e = 0; e < 4; e++) {
                    const int k  = q4 * 4 + e;
                    const uint32_t hb = tf32_rna(fv[e]);
                    const float lo = fv[e] - __uint_as_float(hb);
                    const uint32_t lb = tf32_rna(lo);
                    const int nn = m & 7, kk = k & 7;
                    const int fl  = (nn << 2) | (kk & 3);
                    const int reg = kk >> 2;
                    const int fi  = (((k >> 3) << 4) + (m >> 3)) * 64 + (fl << 1) + reg;
                    BHI[fi] = hb; BLO[fi] = lb;
                }
            }
        }
        __syncthreads();

        // mainloop: 8 ksteps of K=8
        #pragma unroll 2
        for (int ks = 0; ks < 8; ks++) {
            uint4 ah[2], al[2];
            #pragma unroll
            for (int mt = 0; mt < 2; mt++) {
                const int atile = ks * 8 + wr * 2 + mt;
                ah[mt] = *(const uint4*)(AHI + atile * 128 + lane * 4);
                al[mt] = *(const uint4*)(ALO + atile * 128 + lane * 4);
            }
            uint2 bh[4], bl[4];
            #pragma unroll
            for (int nt = 0; nt < 4; nt++) {
                const int btile = ks * 16 + wc * 4 + nt;
                bh[nt] = *(const uint2*)(BHI + btile * 64 + lane * 2);
                bl[nt] = *(const uint2*)(BLO + btile * 64 + lane * 2);
            }
            #pragma unroll
            for (int mt = 0; mt < 2; mt++) {
                #pragma unroll
                for (int nt = 0; nt < 4; nt++) {
                    mma8(acc[mt][nt], (const uint32_t*)&ah[mt], (const uint32_t*)&bh[nt]);
                    mma8(acc[mt][nt], (const uint32_t*)&ah[mt], (const uint32_t*)&bl[nt]);
                    mma8(acc[mt][nt], (const uint32_t*)&al[mt], (const uint32_t*)&bh[nt]);
                }
            }
        }
    }

    // ---- epilogue ----
    #pragma unroll
    for (int mt = 0; mt < 2; mt++) {
        const int lr0 = wr * 32 + mt * 16 + grp;   // local tile rows
        const int lr1 = lr0 + 8;
        const float* Ar0 = A + (size_t)(row0 + lr0) * KDIM;
        const float* Ar1 = A + (size_t)(row0 + lr1) * KDIM;
        #pragma unroll
        for (int nt = 0; nt < 4; nt++) {
            const int lc0 = wc * 32 + nt * 8 + 2 * tig;
            const float* Bc0 = A + (size_t)(col0 + lc0) * KDIM;
            const float* Bc1 = A + (size_t)(col0 + lc0 + 1) * KDIM;

            const float v0 = finish(acc[mt][nt][0], Ar0, Bc0);
            const float v1 = finish(acc[mt][nt][1], Ar0, Bc1);
            const float v2 = finish(acc[mt][nt][2], Ar1, Bc0);
            const float v3 = finish(acc[mt][nt][3], Ar1, Bc1);

            float* p0 = C + (size_t)(row0 + lr0) * NNODE + (col0 + lc0);
            float* p1 = C + (size_t)(row0 + lr1) * NNODE + (col0 + lc0);
            *(float2*)p0 = make_float2(v0, v1);
            *(float2*)p1 = make_float2(v2, v3);

            if (mirror) {
                float* m0 = C + (size_t)(col0 + lc0)     * NNODE + (row0 + lr0);
                float* m1 = C + (size_t)(col0 + lc0 + 1) * NNODE + (row0 + lr0);
                m0[0] = v0; m0[8] = v2;   // rows lr0, lr1 = +8
                m1[0] = v1; m1[8] = v3;
            }
        }
    }
}

extern "C" void kernel_launch(void* const* d_in, const int* in_sizes, int n_in,
                              void* d_out, int out_size)
{
    (void)in_sizes; (void)n_in; (void)out_size;
    const float* nodes = (const float*)d_in[0];
    float* out = (float*)d_out;

    static int cfg = 0;
    if (!cfg) {
        cudaError_t e = cudaFuncSetAttribute(bridge_tf32_kernel,
                                             cudaFuncAttributeMaxDynamicSharedMemorySize,
                                             (int)SMEM_TOTAL);
        if (e == cudaSuccess) cfg = 1;
    }

    dim3 grid(NPAIRS, GROUPS);   // 528 x 4 = 2112 CTAs
    bridge_tf32_kernel<<<grid, NTHREADS, SMEM_TOTAL>>>(nodes, out);
}

// round 17
// speedup vs baseline: 1.1692x; 1.1692x over previous
#include <cuda_runtime.h>
#include <math.h>
#include <stdint.h>

// Problem constants
#define GROUPS 4
#define NNODE  4096
#define KDIM   128
#define TILE   128
#define NB     (NNODE / TILE)
#define NPAIRS (NB * (NB + 1) / 2)   // 528
#define NTHREADS 512

#define T_LOGIT    0.40546510810816f
#define FIX_EPS    1e-3f
#define XPREFILTER 0.4f

// ---- fragment scratch (device globals; allocation-free) ----
// A-frag tiles: g(4) x rb(32) x kstep(16) x mtile(8)  = 16384 tiles x 128 u32
// B-frag tiles: g(4) x rb(32) x kstep(16) x ntile(16) = 32768 tiles x  64 u32
#define ATILES (GROUPS * 32 * 16 * 8)
#define BTILES (GROUPS * 32 * 16 * 16)
__device__ uint32_t g_ahi[ATILES * 128];
__device__ uint32_t g_alo[ATILES * 128];
__device__ uint32_t g_bhi[BTILES * 64];
__device__ uint32_t g_blo[BTILES * 64];

__device__ __forceinline__ uint32_t tf32_rna(float f) {
    uint32_t r; asm("cvt.rna.tf32.f32 %0, %1;" : "=r"(r) : "f"(f)); return r;
}

// mma.sync m16n8k8 tf32 (base sm_103-legal; tcgen05 is sm_103a-only and the
// harness targets plain sm_103 — R14 finding)
__device__ __forceinline__ void mma8(float* d, const uint32_t* a, const uint32_t* b) {
    asm("mma.sync.aligned.m16n8k8.row.col.f32.tf32.tf32.f32 "
        "{%0,%1,%2,%3}, {%4,%5,%6,%7}, {%8,%9}, {%0,%1,%2,%3};"
        : "+f"(d[0]), "+f"(d[1]), "+f"(d[2]), "+f"(d[3])
        : "r"(a[0]), "r"(a[1]), "r"(a[2]), "r"(a[3]), "r"(b[0]), "r"(b[1]));
}

// exact fp32 dot, k-ascending fmaf — validated arithmetic (5 passing benches)
__device__ __noinline__ float exact_dot(const float* __restrict__ a, const float* __restrict__ b) {
    float acc = 0.0f;
    #pragma unroll 4
    for (int k = 0; k < KDIM; k++) acc = fmaf(a[k], b[k], acc);
    return acc;
}

__device__ __forceinline__ float finish(float x, const float* __restrict__ Arow,
                                        const float* __restrict__ Brow) {
    if (fabsf(x - T_LOGIT) < FIX_EPS) x = exact_dot(Arow, Brow);   // flip-proof
    float r = 0.0f;
    if (x > XPREFILTER) {
        const float s = 1.0f / (1.0f + expf(-x));
        r = (s < 0.6f) ? 0.0f : s;
    }
    return r;
}

// ===================== kernel 1: split fp32 -> hi/lo tf32 fragments =====================
// One warp per fragment tile; writes are lane-contiguous (coalesced STG.128/64).
// Fragment layout identical to R15's validated in-smem layout.
__global__ __launch_bounds__(256)
void split_kernel(const float* __restrict__ nodes)
{
    const int W    = (blockIdx.x * blockDim.x + threadIdx.x) >> 5;
    const int lane = threadIdx.x & 31;

    if (W < ATILES) {
        // A tile: m16 x k8.  lane=fl=((r&7)<<2)|(c&3); reg=(r>>3)|((c>>2)<<1)
        const int mtile = W & 7, kstep = (W >> 3) & 15, rb = (W >> 7) & 31, gg = W >> 12;
        const float* base = nodes + ((size_t)gg * NNODE + rb * 128 + mtile * 16) * KDIM + kstep * 8;
        uint32_t hi[4], lo[4];
        #pragma unroll
        for (int reg = 0; reg < 4; reg++) {
            const int r = (lane >> 2) + 8 * (reg & 1);
            const int c = (lane & 3) + 4 * (reg >> 1);
            const float v = base[(size_t)r * KDIM + c];
            hi[reg] = tf32_rna(v);
            lo[reg] = tf32_rna(v - __uint_as_float(hi[reg]));   // subtraction exact
        }
        *(uint4*)(g_ahi + (size_t)W * 128 + lane * 4) = make_uint4(hi[0], hi[1], hi[2], hi[3]);
        *(uint4*)(g_alo + (size_t)W * 128 + lane * 4) = make_uint4(lo[0], lo[1], lo[2], lo[3]);
    } else {
        // B tile: n8 x k8.  lane=fl=(nn<<2)|(kk&3); reg=kk>>2
        const int V = W - ATILES;
        if (V >= BTILES) return;
        const int ntile = V & 15, kstep = (V >> 4) & 15, rb = (V >> 8) & 31, gg = V >> 13;
        const float* base = nodes + ((size_t)gg * NNODE + rb * 128 + ntile * 8) * KDIM + kstep * 8;
        uint32_t hi[2], lo[2];
        #pragma unroll
        for (int reg = 0; reg < 2; reg++) {
            const int nn = lane >> 2;
            const int kk = (lane & 3) + 4 * reg;
            const float v = base[(size_t)nn * KDIM + kk];
            hi[reg] = tf32_rna(v);
            lo[reg] = tf32_rna(v - __uint_as_float(hi[reg]));
        }
        *(uint2*)(g_bhi + (size_t)V * 64 + lane * 2) = make_uint2(hi[0], hi[1]);
        *(uint2*)(g_blo + (size_t)V * 64 + lane * 2) = make_uint2(lo[0], lo[1]);
    }
}

// ===================== kernel 2: fragment-fed tf32 GEMM =====================
__global__ __launch_bounds__(NTHREADS, 1)
void bridge_tf32_kernel(const float* __restrict__ nodes, float* __restrict__ out)
{
    // ---- upper-triangle block pair (bi <= bj) ----
    const int t = blockIdx.x;
    int bi = (int)((float)NB + 0.5f - sqrtf(((float)NB + 0.5f) * ((float)NB + 0.5f) - 2.0f * (float)t));
    if (bi < 0) bi = 0;
    if (bi >= NB) bi = NB - 1;
    while (bi + 1 <= NB - 1 && ((bi + 1) * NB - (bi + 1) * bi / 2) <= t) bi++;
    while (bi > 0 && (bi * NB - bi * (bi - 1) / 2) > t) bi--;
    const int bj = bi + (t - (bi * NB - bi * (bi - 1) / 2));

    const int g    = blockIdx.y;
    const int row0 = bi * TILE;
    const int col0 = bj * TILE;
    const bool mirror = (bi != bj);

    const float* __restrict__ A = nodes + (size_t)g * NNODE * KDIM;
    float* __restrict__ C       = out   + (size_t)g * NNODE * (size_t)NNODE;

    const int tid  = threadIdx.x;
    const int wid  = tid >> 5;
    const int lane = tid & 31;
    const int grp  = lane >> 2;
    const int tig  = lane & 3;
    const int wr   = wid >> 2;        // warp row 0..3
    const int wc   = wid & 3;         // warp col 0..3

    // fragment bases for this CTA's row-block (A) and col-block (B)
    const uint32_t* __restrict__ ahi = g_ahi + ((size_t)(g * 32 + bi) * 16) * 8 * 128;
    const uint32_t* __restrict__ alo = g_alo + ((size_t)(g * 32 + bi) * 16) * 8 * 128;
    const uint32_t* __restrict__ bhi = g_bhi + ((size_t)(g * 32 + bj) * 16) * 16 * 64;
    const uint32_t* __restrict__ blo = g_blo + ((size_t)(g * 32 + bj) * 16) * 16 * 64;

    float acc[2][4][4];
    #pragma unroll
    for (int i = 0; i < 2; i++)
        #pragma unroll
        for (int j = 0; j < 4; j++)
            #pragma unroll
            for (int q = 0; q < 4; q++)
                acc[i][j][q] = 0.0f;

    // ---- mainloop: 16 ksteps, pure LDG + MMA (no smem, no syncs) ----
    #pragma unroll 2
    for (int ks = 0; ks < 16; ks++) {
        uint4 ah[2], al[2];
        #pragma unroll
        for (int mt = 0; mt < 2; mt++) {
            const size_t ao = ((size_t)ks * 8 + wr * 2 + mt) * 128 + lane * 4;
            ah[mt] = *(const uint4*)(ahi + ao);
            al[mt] = *(const uint4*)(alo + ao);
        }
        uint2 bh[4], bl[4];
        #pragma unroll
        for (int nt = 0; nt < 4; nt++) {
            const size_t bo = ((size_t)ks * 16 + wc * 4 + nt) * 64 + lane * 2;
            bh[nt] = *(const uint2*)(bhi + bo);
            bl[nt] = *(const uint2*)(blo + bo);
        }
        #pragma unroll
        for (int mt = 0; mt < 2; mt++) {
            #pragma unroll
            for (int nt = 0; nt < 4; nt++) {
                mma8(acc[mt][nt], (const uint32_t*)&ah[mt], (const uint32_t*)&bh[nt]);
                mma8(acc[mt][nt], (const uint32_t*)&ah[mt], (const uint32_t*)&bl[nt]);
                mma8(acc[mt][nt], (const uint32_t*)&al[mt], (const uint32_t*)&bh[nt]);
            }
        }
    }

    // ---- epilogue (layout validated in R15) ----
    #pragma unroll
    for (int mt = 0; mt < 2; mt++) {
        const int lr0 = wr * 32 + mt * 16 + grp;
        const int lr1 = lr0 + 8;
        const float* Ar0 = A + (size_t)(row0 + lr0) * KDIM;
        const float* Ar1 = A + (size_t)(row0 + lr1) * KDIM;
        #pragma unroll
        for (int nt = 0; nt < 4; nt++) {
            const int lc0 = wc * 32 + nt * 8 + 2 * tig;
            const float* Bc0 = A + (size_t)(col0 + lc0) * KDIM;
            const float* Bc1 = A + (size_t)(col0 + lc0 + 1) * KDIM;

            const float v0 = finish(acc[mt][nt][0], Ar0, Bc0);
            const float v1 = finish(acc[mt][nt][1], Ar0, Bc1);
            const float v2 = finish(acc[mt][nt][2], Ar1, Bc0);
            const float v3 = finish(acc[mt][nt][3], Ar1, Bc1);

            float* p0 = C + (size_t)(row0 + lr0) * NNODE + (col0 + lc0);
            float* p1 = C + (size_t)(row0 + lr1) * NNODE + (col0 + lc0);
            *(float2*)p0 = make_float2(v0, v1);
            *(float2*)p1 = make_float2(v2, v3);

            if (mirror) {
                float* m0 = C + (size_t)(col0 + lc0)     * NNODE + (row0 + lr0);
                float* m1 = C + (size_t)(col0 + lc0 + 1) * NNODE + (row0 + lr0);
                m0[0] = v0; m0[8] = v2;
                m1[0] = v1; m1[8] = v3;
            }
        }
    }
}

extern "C" void kernel_launch(void* const* d_in, const int* in_sizes, int n_in,
                              void* d_out, int out_size)
{
    (void)in_sizes; (void)n_in; (void)out_size;
    const float* nodes = (const float*)d_in[0];
    float* out = (float*)d_out;

    // kernel 1: build tf32 hi/lo fragments (one warp per tile)
    const int total_warps = ATILES + BTILES;          // 49152
    const int blocks = (total_warps * 32 + 255) / 256;  // 6144
    split_kernel<<<blocks, 256>>>(nodes);

    // kernel 2: fragment-fed GEMM + sigmoid/threshold epilogue
    dim3 grid(NPAIRS, GROUPS);   // 528 x 4 = 2112 CTAs
    bridge_tf32_kernel<<<grid, NTHREADS>>>(nodes, out);
}